// round 16
// baseline (speedup 1.0000x reference)
#include <cuda_runtime.h>
#include <cuda.h>
#include <cuda_fp16.h>
#include <math.h>
#include <stdint.h>

// Problem constants
#define BATCH 2
#define LSEQ 2048
#define DMODEL 1024
#define DINNER 2048
#define DSTATE 16
#define DTRANK 128
#define ROWS (BATCH * LSEQ)           // 4096
#define XPROJ_N (DTRANK + 2 * DSTATE) // 160
#define CHUNKS 32
#define CLEN (LSEQ / CHUNKS)          // 64
#define KSPLIT 4
#define XPN (ROWS * XPROJ_N)          // 655360

// Scratch (device globals: allocation-free rule)
__device__ __half g_xzh[(size_t)ROWS * (2 * DINNER)];
__device__ __half g_uh[(size_t)ROWS * DINNER];
__device__ float  g_xdbl[(size_t)ROWS * XPROJ_N];
__device__ float  g_xp4[(size_t)KSPLIT * XPN];
__device__ __half g_dtin_h[(size_t)ROWS * DTRANK];
__device__ __half g_dth[(size_t)ROWS * DINNER];
__device__ __half g_yh[(size_t)ROWS * DINNER];
__device__ __half g_xh[(size_t)ROWS * DMODEL];
__device__ __half g_w1h[(size_t)(2 * DINNER) * DMODEL];
__device__ __half g_w2h[(size_t)XPROJ_N * DINNER];
__device__ __half g_w3h[(size_t)DINNER * DTRANK];
__device__ __half g_w4h[(size_t)DMODEL * DINNER];
__device__ float  g_hpart[(size_t)BATCH * CHUNKS * DSTATE * DINNER];
__device__ float  g_hstart[(size_t)BATCH * CHUNKS * DSTATE * DINNER];
__device__ float  g_S[(size_t)BATCH * CHUNKS * DINNER];

// ---------------------------------------------------------------------------
// helpers
// ---------------------------------------------------------------------------
__device__ __forceinline__ void cp_async16(uint32_t saddr, const void* g) {
    asm volatile("cp.async.cg.shared.global [%0], [%1], 16;\n" :: "r"(saddr), "l"(g));
}
__device__ __forceinline__ void cp_async16_zfill(uint32_t saddr, const void* g, bool pred) {
    int sz = pred ? 16 : 0;
    asm volatile("cp.async.cg.shared.global [%0], [%1], 16, %2;\n" :: "r"(saddr), "l"(g), "r"(sz));
}
__device__ __forceinline__ void ldsm_x4(uint32_t& r0, uint32_t& r1, uint32_t& r2,
                                        uint32_t& r3, uint32_t addr) {
    asm volatile("ldmatrix.sync.aligned.m8n8.x4.shared.b16 {%0,%1,%2,%3}, [%4];"
                 : "=r"(r0), "=r"(r1), "=r"(r2), "=r"(r3) : "r"(addr));
}

#define MBARRIER_INIT(mbar, count) \
    asm volatile("mbarrier.init.shared.b64 [%0], %1;" :: "r"((uint32_t)(mbar)), "r"((uint32_t)(count)) : "memory")
#define MBARRIER_EXPECT_TX(mbar, tx) \
    asm volatile("mbarrier.arrive.expect_tx.shared.b64 _, [%0], %1;" :: "r"((uint32_t)(mbar)), "r"((uint32_t)(tx)) : "memory")
#define MBARRIER_ARRIVE(mbar) \
    asm volatile("mbarrier.arrive.shared.b64 _, [%0];" :: "r"((uint32_t)(mbar)) : "memory")
#define MBARRIER_WAIT_PARITY(mbar_smem_addr, phase_parity) do { \
    uint32_t _mbar = (uint32_t)(mbar_smem_addr); \
    uint32_t _parity = (uint32_t)(phase_parity); \
    uint32_t _done; \
    asm volatile("{\n\t.reg .pred p;\n\t" \
        "mbarrier.try_wait.parity.acquire.cta.shared::cta.b64 p, [%1], %2;\n\t" \
        "selp.b32 %0, 1, 0, p;\n\t}" \
        : "=r"(_done) : "r"(_mbar), "r"(_parity) : "memory"); \
    if (!_done) { \
        asm volatile("{\n\t.reg .pred P1;\n\t" \
            "WAIT_LOOP_%=:\n\t" \
            "mbarrier.try_wait.parity.acquire.cta.shared::cta.b64 P1, [%0], %1, 0x989680;\n\t" \
            "@P1 bra.uni WAIT_DONE_%=;\n\t" \
            "bra.uni WAIT_LOOP_%=;\n\t" \
            "WAIT_DONE_%=:\n\t}" \
            :: "r"(_mbar), "r"(_parity) : "memory"); \
    } \
} while(0)

__device__ __forceinline__ void tma_load_2d(uint32_t smem_addr, const CUtensorMap* map,
                                            int cx, int cy, uint32_t mbar) {
    asm volatile(
        "cp.async.bulk.tensor.2d.shared::cta.global.tile.mbarrier::complete_tx::bytes "
        "[%0], [%1, {%2, %3}], [%4];"
        :: "r"(smem_addr), "l"(map), "r"(cx), "r"(cy), "r"(mbar) : "memory");
}

// ===========================================================================
// TMA-fed fp16 GEMM: C[M,N] = epi( A[M,K] @ B[N,K]^T ), BM=BN=128, BK=64,
// 3 stages, SW128 tiles (128B rows), ring pipeline with full/empty mbarriers:
// consumers (8 warps) arrive on empty[s] after their MMAs (no __syncthreads);
// producer (tid 0) waits empty[s] then refills via TMA. Tile bases are
// 1024B-aligned (SW128 swizzle uses absolute smem address bits).
// De-swizzle: xorv=(lane&7)<<4 (row&7==lane&7 for every fragment).
// EPI: 0 fp32 C; 3 fp16 Ch; 4 split-K fp32 partial; 5 softplus+bias fp16 Ch.
// ===========================================================================
#define TSTG 3
#define T_TILE 16384                    // 128 rows x 128B
#define T_STAGE (2 * T_TILE)            // A + B = 32768
#define TSMEM_BYTES (2048 + TSTG * T_STAGE)   // 100352 (incl. align slack)

template <int EPI>
__global__ __launch_bounds__(256, 2) void tma_hgemm(
    const __grid_constant__ CUtensorMap tmA,
    const __grid_constant__ CUtensorMap tmB,
    float* __restrict__ C, const float* __restrict__ bias,
    __half* __restrict__ Ch,
    int M, int N, int K, int ldc)
{
    extern __shared__ __align__(1024) char tsm[];
    const uint32_t sb = (uint32_t)__cvta_generic_to_shared(tsm);
    const int tid  = threadIdx.x;
    const int wid  = tid >> 5;
    const int lane = tid & 31;
    const int g    = lane >> 2;
    const int tg   = lane & 3;
    const int m0 = blockIdx.y * 128;
    const int n0 = blockIdx.x * 128;
    const int wm = (wid >> 2) * 64;
    const int wn = (wid & 3) * 32;
    const int kbase = blockIdx.z * K;
    const int nk = K / 64;

    const int lrow8 = ((lane >> 3) & 1) * 8 + (lane & 7);     // 0..15
    const uint32_t c16  = (uint32_t)((lane >> 4) * 16);       // 0 or 16
    const uint32_t xorv = (uint32_t)((lane & 7) << 4);        // SW128 de-swizzle
    const uint32_t stage0 = (sb + 64 + 1023) & ~1023u;        // 1024B-aligned!
    const uint32_t aLane = (uint32_t)((wm + lrow8) * 128);
    const uint32_t bLane = (uint32_t)((wn + lrow8) * 128);
    // mbarriers: full[s] at sb+8s, empty[s] at sb+32+8s
    const uint32_t fullB = sb;
    const uint32_t emptyB = sb + 32;

    if (tid == 0) {
#pragma unroll
        for (int s = 0; s < TSTG; s++) {
            MBARRIER_INIT(fullB + 8 * s, 1);
            MBARRIER_INIT(emptyB + 8 * s, 8);
        }
    }
    __syncthreads();

    // prologue: fill ALL stages
    if (tid == 0) {
#pragma unroll
        for (int t = 0; t < TSTG; t++) {
            if (t < nk) {
                uint32_t bar = fullB + 8 * t;
                uint32_t da = stage0 + t * T_STAGE;
                MBARRIER_EXPECT_TX(bar, T_STAGE);
                tma_load_2d(da, &tmA, kbase + t * 64, m0, bar);
                tma_load_2d(da + T_TILE, &tmB, kbase + t * 64, n0, bar);
            }
        }
    }

    float acc[4][4][4];
#pragma unroll
    for (int i = 0; i < 4; i++)
#pragma unroll
        for (int j = 0; j < 4; j++)
#pragma unroll
            for (int r = 0; r < 4; r++) acc[i][j][r] = 0.f;

    int s = 0, ph = 0;
    for (int t = 0; t < nk; t++) {
        MBARRIER_WAIT_PARITY(fullB + 8 * s, ph);
        const uint32_t aS = stage0 + s * T_STAGE;
        const uint32_t bS = aS + T_TILE;
#pragma unroll
        for (int ks = 0; ks < 4; ks++) {
            const uint32_t col = ((uint32_t)(ks * 32) + c16) ^ xorv;
            uint32_t af[4][4];
#pragma unroll
            for (int mi = 0; mi < 4; mi++)
                ldsm_x4(af[mi][0], af[mi][1], af[mi][2], af[mi][3],
                        aS + aLane + mi * 2048 + col);
            uint32_t bf[4][2];
#pragma unroll
            for (int n2 = 0; n2 < 2; n2++) {
                uint32_t b0, b1, b2, b3;
                ldsm_x4(b0, b1, b2, b3, bS + bLane + n2 * 2048 + col);
                bf[2 * n2][0] = b0; bf[2 * n2 + 1][0] = b1;
                bf[2 * n2][1] = b2; bf[2 * n2 + 1][1] = b3;
            }
#pragma unroll
            for (int mi = 0; mi < 4; mi++)
#pragma unroll
                for (int ni = 0; ni < 4; ni++) {
                    asm volatile(
                        "mma.sync.aligned.m16n8k16.row.col.f32.f16.f16.f32 "
                        "{%0,%1,%2,%3}, {%4,%5,%6,%7}, {%8,%9}, {%0,%1,%2,%3};"
                        : "+f"(acc[mi][ni][0]), "+f"(acc[mi][ni][1]),
                          "+f"(acc[mi][ni][2]), "+f"(acc[mi][ni][3])
                        : "r"(af[mi][0]), "r"(af[mi][1]), "r"(af[mi][2]), "r"(af[mi][3]),
                          "r"(bf[ni][0]), "r"(bf[ni][1]));
                }
        }
        // All LDSM results for stage s have been consumed by MMA issue; this
        // warp is done reading the stage. Arrive on empty[s] (count 8).
        if (lane == 0) MBARRIER_ARRIVE(emptyB + 8 * s);
        // Producer: once all 8 warps have arrived, refill stage s.
        if (tid == 0 && t + TSTG < nk) {
            MBARRIER_WAIT_PARITY(emptyB + 8 * s, ph);
            MBARRIER_EXPECT_TX(fullB + 8 * s, T_STAGE);
            tma_load_2d(aS, &tmA, kbase + (t + TSTG) * 64, m0, fullB + 8 * s);
            tma_load_2d(bS, &tmB, kbase + (t + TSTG) * 64, n0, fullB + 8 * s);
        }
        if (++s == TSTG) { s = 0; ph ^= 1; }
    }

    float* Cw = C;
    if (EPI == 4) Cw = C + (size_t)blockIdx.z * M * ldc;

#pragma unroll
    for (int mi = 0; mi < 4; mi++) {
        int r0 = m0 + wm + mi * 16 + g;
#pragma unroll
        for (int ni = 0; ni < 4; ni++) {
            int c0 = n0 + wn + ni * 8 + 2 * tg;
            if (c0 >= N) continue;
#pragma unroll
            for (int hh = 0; hh < 2; hh++) {
                int row = r0 + hh * 8;
                float v0 = acc[mi][ni][hh * 2 + 0];
                float v1 = acc[mi][ni][hh * 2 + 1];
                if (EPI == 5) {
                    v0 += bias[c0];     v1 += bias[c0 + 1];
                    v0 = (v0 > 20.f) ? v0 : log1pf(__expf(v0));
                    v1 = (v1 > 20.f) ? v1 : log1pf(__expf(v1));
                    *(__half2*)(Ch + (size_t)row * ldc + c0) = __floats2half2_rn(v0, v1);
                } else if (EPI == 3) {
                    *(__half2*)(Ch + (size_t)row * ldc + c0) = __floats2half2_rn(v0, v1);
                } else {
                    *(float2*)(Cw + (size_t)row * ldc + c0) = make_float2(v0, v1);
                }
            }
        }
    }
}

// ===========================================================================
// Fallback fp16 GEMM (R9 config, proven): cp.async 4-stage, BK=32, LDH=40.
// ===========================================================================
#define BKH 32
#define PADH 8
#define LDH (BKH + PADH)
#define NSTG 4
#define HSMEM_BYTES (2 * NSTG * 128 * LDH * 2)   // 81920

template <int EPI>
__global__ __launch_bounds__(256, 2) void hgemm_nt(
    const __half* __restrict__ A, const __half* __restrict__ B,
    float* __restrict__ C, const float* __restrict__ bias,
    __half* __restrict__ Ch,
    int M, int N, int K, int lda, int ldb, int ldc)
{
    extern __shared__ __half sh[];
    __half (*As)[128][LDH] = (__half(*)[128][LDH])sh;
    __half (*Bs)[128][LDH] = (__half(*)[128][LDH])(sh + NSTG * 128 * LDH);

    const int tid  = threadIdx.x;
    const int wid  = tid >> 5;
    const int lane = tid & 31;
    const int g    = lane >> 2;
    const int tg   = lane & 3;
    const int m0 = blockIdx.y * 128;
    const int n0 = blockIdx.x * 128;
    const int wm = (wid >> 2) * 64;
    const int wn = (wid & 3) * 32;

    const int kbase = blockIdx.z * K;
    A += kbase;
    B += kbase;

    const int lrow8 = ((lane >> 3) & 1) * 8 + (lane & 7);
    const int lcol8 = (lane >> 4) * 8;
    const uint32_t aBase = (uint32_t)__cvta_generic_to_shared(&As[0][wm + lrow8][lcol8]);
    const uint32_t bBase = (uint32_t)__cvta_generic_to_shared(&Bs[0][wn + lrow8][lcol8]);
    const uint32_t STG_STRIDE = 128 * LDH * 2;
    const uint32_t ROW16 = 16 * LDH * 2;

    float acc[4][4][4];
#pragma unroll
    for (int i = 0; i < 4; i++)
#pragma unroll
        for (int j = 0; j < 4; j++)
#pragma unroll
            for (int r = 0; r < 4; r++) acc[i][j][r] = 0.f;

    auto load_tiles = [&](int s, int k0) {
#pragma unroll
        for (int h = 0; h < 2; h++) {
            int idx = tid + h * 256;
            int row = idx >> 2;
            int ch  = idx & 3;
            uint32_t da = (uint32_t)__cvta_generic_to_shared(&As[s][row][ch * 8]);
            cp_async16(da, A + (size_t)(m0 + row) * lda + k0 + ch * 8);
            uint32_t db = (uint32_t)__cvta_generic_to_shared(&Bs[s][row][ch * 8]);
            int brow = n0 + row;
            const __half* src = B + (size_t)(brow < N ? brow : 0) * ldb + k0 + ch * 8;
            cp_async16_zfill(db, src, brow < N);
        }
    };

    const int nk = K / BKH;
#pragma unroll
    for (int t = 0; t < NSTG - 1; t++) {
        if (t < nk) load_tiles(t, t * BKH);
        asm volatile("cp.async.commit_group;\n" ::: "memory");
    }

    for (int t = 0; t < nk; t++) {
        const int s = t % NSTG;
        asm volatile("cp.async.wait_group %0;\n" :: "n"(NSTG - 2) : "memory");
        __syncthreads();
        if (t + NSTG - 1 < nk) load_tiles((t + NSTG - 1) % NSTG, (t + NSTG - 1) * BKH);
        asm volatile("cp.async.commit_group;\n" ::: "memory");

        const uint32_t aS = aBase + s * STG_STRIDE;
        const uint32_t bS = bBase + s * STG_STRIDE;
#pragma unroll
        for (int ks = 0; ks < 2; ks++) {
            const uint32_t kkb = ks * 32;
            uint32_t af[4][4];
#pragma unroll
            for (int mi = 0; mi < 4; mi++)
                ldsm_x4(af[mi][0], af[mi][1], af[mi][2], af[mi][3],
                        aS + mi * ROW16 + kkb);
            uint32_t bf[4][2];
#pragma unroll
            for (int n2 = 0; n2 < 2; n2++) {
                uint32_t b0, b1, b2, b3;
                ldsm_x4(b0, b1, b2, b3, bS + n2 * ROW16 + kkb);
                bf[2 * n2][0] = b0; bf[2 * n2 + 1][0] = b1;
                bf[2 * n2][1] = b2; bf[2 * n2 + 1][1] = b3;
            }
#pragma unroll
            for (int mi = 0; mi < 4; mi++)
#pragma unroll
                for (int ni = 0; ni < 4; ni++) {
                    asm volatile(
                        "mma.sync.aligned.m16n8k16.row.col.f32.f16.f16.f32 "
                        "{%0,%1,%2,%3}, {%4,%5,%6,%7}, {%8,%9}, {%0,%1,%2,%3};"
                        : "+f"(acc[mi][ni][0]), "+f"(acc[mi][ni][1]),
                          "+f"(acc[mi][ni][2]), "+f"(acc[mi][ni][3])
                        : "r"(af[mi][0]), "r"(af[mi][1]), "r"(af[mi][2]), "r"(af[mi][3]),
                          "r"(bf[ni][0]), "r"(bf[ni][1]));
                }
        }
    }

    float* Cw = C;
    if (EPI == 4) Cw = C + (size_t)blockIdx.z * M * ldc;

#pragma unroll
    for (int mi = 0; mi < 4; mi++) {
        int r0 = m0 + wm + mi * 16 + g;
#pragma unroll
        for (int ni = 0; ni < 4; ni++) {
            int c0 = n0 + wn + ni * 8 + 2 * tg;
            if (c0 >= N) continue;
#pragma unroll
            for (int hh = 0; hh < 2; hh++) {
                int row = r0 + hh * 8;
                float v0 = acc[mi][ni][hh * 2 + 0];
                float v1 = acc[mi][ni][hh * 2 + 1];
                if (EPI == 5) {
                    v0 += bias[c0];     v1 += bias[c0 + 1];
                    v0 = (v0 > 20.f) ? v0 : log1pf(__expf(v0));
                    v1 = (v1 > 20.f) ? v1 : log1pf(__expf(v1));
                    *(__half2*)(Ch + (size_t)row * ldc + c0) = __floats2half2_rn(v0, v1);
                } else if (EPI == 3) {
                    *(__half2*)(Ch + (size_t)row * ldc + c0) = __floats2half2_rn(v0, v1);
                } else {
                    *(float2*)(Cw + (size_t)row * ldc + c0) = make_float2(v0, v1);
                }
            }
        }
    }
}

// ---------------------------------------------------------------------------
// x_proj split-K reduce: xdbl = sum of 4 partials; dtin_h = fp16 of cols<128
// ---------------------------------------------------------------------------
__global__ __launch_bounds__(256) void xproj_reduce(
    const float* __restrict__ part, float* __restrict__ xdbl,
    __half* __restrict__ dtin)
{
    int i = blockIdx.x * blockDim.x + threadIdx.x;
    if (i >= XPN / 4) return;
    const float4* p = (const float4*)part;
    float4 v = p[i];
    float4 a = p[i + XPN / 4];
    float4 b = p[i + 2 * (XPN / 4)];
    float4 c = p[i + 3 * (XPN / 4)];
    v.x += a.x + b.x + c.x;
    v.y += a.y + b.y + c.y;
    v.z += a.z + b.z + c.z;
    v.w += a.w + b.w + c.w;
    ((float4*)xdbl)[i] = v;
    int col4 = (i % (XPROJ_N / 4)) * 4;
    if (col4 < DTRANK) {
        int row = i / (XPROJ_N / 4);
        __half2 h[2] = { __floats2half2_rn(v.x, v.y), __floats2half2_rn(v.z, v.w) };
        *(uint2*)(dtin + (size_t)row * DTRANK + col4) = *(uint2*)h;
    }
}

// ---------------------------------------------------------------------------
// fused fp32 -> fp16 conversion of x + 4 weight matrices (one launch)
// ---------------------------------------------------------------------------
#define NG_X  (ROWS * DMODEL / 8)
#define NG_W1 (2 * DINNER * DMODEL / 8)
#define NG_W2 (XPROJ_N * DINNER / 8)
#define NG_W3 (DINNER * DTRANK / 8)
#define NG_W4 (DMODEL * DINNER / 8)
#define NG_TOT (NG_X + NG_W1 + NG_W2 + NG_W3 + NG_W4)

__device__ __forceinline__ void cvt8(const float* in, __half* out, int i) {
    const float4* p = (const float4*)in + (size_t)i * 2;
    float4 a = p[0], b = p[1];
    __half2 h[4];
    h[0] = __floats2half2_rn(a.x, a.y);
    h[1] = __floats2half2_rn(a.z, a.w);
    h[2] = __floats2half2_rn(b.x, b.y);
    h[3] = __floats2half2_rn(b.z, b.w);
    ((uint4*)out)[i] = *(uint4*)h;
}

__global__ __launch_bounds__(256) void cvt_all_kernel(
    const float* __restrict__ x,  __half* __restrict__ xh,
    const float* __restrict__ w1, __half* __restrict__ w1h,
    const float* __restrict__ w2, __half* __restrict__ w2h,
    const float* __restrict__ w3, __half* __restrict__ w3h,
    const float* __restrict__ w4, __half* __restrict__ w4h)
{
    int i = blockIdx.x * blockDim.x + threadIdx.x;
    if (i < NG_X)                           { cvt8(x, xh, i); return; }
    i -= NG_X;
    if (i < NG_W1)                          { cvt8(w1, w1h, i); return; }
    i -= NG_W1;
    if (i < NG_W2)                          { cvt8(w2, w2h, i); return; }
    i -= NG_W2;
    if (i < NG_W3)                          { cvt8(w3, w3h, i); return; }
    i -= NG_W3;
    if (i < NG_W4)                          { cvt8(w4, w4h, i); }
}

// ---------------------------------------------------------------------------
// Causal depthwise conv1d (d_conv=4) + bias + SiLU -> u_h (fp16 only)
// ---------------------------------------------------------------------------
__global__ __launch_bounds__(256) void conv_silu_kernel(
    const __half* __restrict__ xzh, const float* __restrict__ w,
    const float* __restrict__ bias, __half* __restrict__ uh)
{
    int idx = blockIdx.x * blockDim.x + threadIdx.x;
    if (idx >= ROWS * DINNER) return;
    int d = idx & (DINNER - 1);
    int row = idx >> 11;
    int l = row & (LSEQ - 1);

    float w0 = w[d * 4 + 0], w1 = w[d * 4 + 1], w2 = w[d * 4 + 2], w3 = w[d * 4 + 3];
    const __half* base = xzh + (size_t)row * (2 * DINNER) + d;
    float acc = bias[d] + w3 * __half2float(base[0]);
    if (l >= 1) acc = fmaf(w2, __half2float(base[-(2 * DINNER)]), acc);
    if (l >= 2) acc = fmaf(w1, __half2float(base[-2 * (2 * DINNER)]), acc);
    if (l >= 3) acc = fmaf(w0, __half2float(base[-3 * (2 * DINNER)]), acc);
    float sact = acc / (1.f + __expf(-acc));
    uh[idx] = __float2half(sact);
}

// ---------------------------------------------------------------------------
// Chunked selective scan (exact chunk decomposition via exp(A * sum dt)).
// ---------------------------------------------------------------------------
__device__ __forceinline__ void load_bc16(const float* __restrict__ p, float* v) {
    float4 a = ((const float4*)p)[0], b2 = ((const float4*)p)[1];
    float4 c = ((const float4*)p)[2], e = ((const float4*)p)[3];
    v[0]=a.x; v[1]=a.y; v[2]=a.z; v[3]=a.w;
    v[4]=b2.x; v[5]=b2.y; v[6]=b2.z; v[7]=b2.w;
    v[8]=c.x; v[9]=c.y; v[10]=c.z; v[11]=c.w;
    v[12]=e.x; v[13]=e.y; v[14]=e.z; v[15]=e.w;
}

__global__ __launch_bounds__(128) void scan_pass1(
    const __half* __restrict__ uh, const __half* __restrict__ dth,
    const float* __restrict__ xdbl, const float* __restrict__ A_log,
    float* __restrict__ hpart, float* __restrict__ Ssum)
{
    const int d = blockIdx.x * 128 + threadIdx.x;
    const int c = blockIdx.y;
    const int b = blockIdx.z;

    float A[DSTATE];
    const float a0 = -__expf(A_log[d * DSTATE]);
    bool structured = true;
#pragma unroll
    for (int n = 0; n < DSTATE; n++) {
        A[n] = -__expf(A_log[d * DSTATE + n]);
        structured = structured &&
            (fabsf(A[n] - (float)(n + 1) * a0) <= 1e-4f * (float)(n + 1));
    }

    float h[DSTATE];
#pragma unroll
    for (int n = 0; n < DSTATE; n++) h[n] = 0.f;
    float S = 0.f;

    const int l0 = c * CLEN;
    if (structured) {
        for (int l = l0; l < l0 + CLEN; l++) {
            const size_t row = (size_t)b * LSEQ + l;
            const float ut  = __half2float(uh[row * DINNER + d]);
            const float dtt = __half2float(dth[row * DINNER + d]);
            float Bv[16];
            load_bc16(xdbl + row * XPROJ_N + DTRANK, Bv);
            S += dtt;
            const float dtu = dtt * ut;
            const float E = __expf(dtt * a0);
            float dA = E;
#pragma unroll
            for (int n = 0; n < DSTATE; n++) {
                h[n] = fmaf(dA, h[n], dtu * Bv[n]);
                dA *= E;
            }
        }
    } else {
        for (int l = l0; l < l0 + CLEN; l++) {
            const size_t row = (size_t)b * LSEQ + l;
            const float ut  = __half2float(uh[row * DINNER + d]);
            const float dtt = __half2float(dth[row * DINNER + d]);
            float Bv[16];
            load_bc16(xdbl + row * XPROJ_N + DTRANK, Bv);
            S += dtt;
            const float dtu = dtt * ut;
#pragma unroll
            for (int n = 0; n < DSTATE; n++)
                h[n] = fmaf(__expf(dtt * A[n]), h[n], dtu * Bv[n]);
        }
    }

    const size_t base = ((size_t)(b * CHUNKS + c) * DSTATE) * DINNER + d;
#pragma unroll
    for (int n = 0; n < DSTATE; n++) hpart[base + (size_t)n * DINNER] = h[n];
    Ssum[(size_t)(b * CHUNKS + c) * DINNER + d] = S;
}

__global__ __launch_bounds__(128) void scan_combine(
    const float* __restrict__ A_log, const float* __restrict__ Ssum,
    const float* __restrict__ hpart, float* __restrict__ hstart)
{
    const int d = blockIdx.x * 128 + threadIdx.x;
    const int n = blockIdx.y;
    const int b = blockIdx.z;
    const float An = -__expf(A_log[d * DSTATE + n]);
    float h = 0.f;
    for (int c = 0; c < CHUNKS; c++) {
        const size_t idx = ((size_t)(b * CHUNKS + c) * DSTATE + n) * DINNER + d;
        hstart[idx] = h;
        const float P = __expf(An * Ssum[(size_t)(b * CHUNKS + c) * DINNER + d]);
        h = fmaf(P, h, hpart[idx]);
    }
}

__global__ __launch_bounds__(128) void scan_pass2(
    const __half* __restrict__ uh, const __half* __restrict__ dth,
    const float* __restrict__ xdbl, const __half* __restrict__ xzh,
    const float* __restrict__ A_log, const float* __restrict__ Dp,
    const float* __restrict__ hstart, __half* __restrict__ yh)
{
    const int d = blockIdx.x * 128 + threadIdx.x;
    const int c = blockIdx.y;
    const int b = blockIdx.z;

    float A[DSTATE];
    const float a0 = -__expf(A_log[d * DSTATE]);
    bool structured = true;
#pragma unroll
    for (int n = 0; n < DSTATE; n++) {
        A[n] = -__expf(A_log[d * DSTATE + n]);
        structured = structured &&
            (fabsf(A[n] - (float)(n + 1) * a0) <= 1e-4f * (float)(n + 1));
    }
    const float Dd = Dp[d];

    float h[DSTATE];
    const size_t hbase = ((size_t)(b * CHUNKS + c) * DSTATE) * DINNER + d;
#pragma unroll
    for (int n = 0; n < DSTATE; n++) h[n] = hstart[hbase + (size_t)n * DINNER];

    const int l0 = c * CLEN;
    if (structured) {
        for (int l = l0; l < l0 + CLEN; l++) {
            const size_t row = (size_t)b * LSEQ + l;
            const float ut  = __half2float(uh[row * DINNER + d]);
            const float dtt = __half2float(dth[row * DINNER + d]);
            const float zt  = __half2float(xzh[row * (2 * DINNER) + DINNER + d]);
            float Bv[16], Cv[16];
            load_bc16(xdbl + row * XPROJ_N + DTRANK, Bv);
            load_bc16(xdbl + row * XPROJ_N + DTRANK + DSTATE, Cv);
            const float dtu = dtt * ut;
            const float E = __expf(dtt * a0);
            float dA = E;
            float acc = 0.f;
#pragma unroll
            for (int n = 0; n < DSTATE; n++) {
                h[n] = fmaf(dA, h[n], dtu * Bv[n]);
                acc = fmaf(h[n], Cv[n], acc);
                dA *= E;
            }
            float yv = fmaf(ut, Dd, acc);
            float sz = zt / (1.f + __expf(-zt));
            yh[row * DINNER + d] = __float2half(yv * sz);
        }
    } else {
        for (int l = l0; l < l0 + CLEN; l++) {
            const size_t row = (size_t)b * LSEQ + l;
            const float ut  = __half2float(uh[row * DINNER + d]);
            const float dtt = __half2float(dth[row * DINNER + d]);
            const float zt  = __half2float(xzh[row * (2 * DINNER) + DINNER + d]);
            float Bv[16], Cv[16];
            load_bc16(xdbl + row * XPROJ_N + DTRANK, Bv);
            load_bc16(xdbl + row * XPROJ_N + DTRANK + DSTATE, Cv);
            const float dtu = dtt * ut;
            float acc = 0.f;
#pragma unroll
            for (int n = 0; n < DSTATE; n++) {
                h[n] = fmaf(__expf(dtt * A[n]), h[n], dtu * Bv[n]);
                acc = fmaf(h[n], Cv[n], acc);
            }
            float yv = fmaf(ut, Dd, acc);
            float sz = zt / (1.f + __expf(-zt));
            yh[row * DINNER + d] = __float2half(yv * sz);
        }
    }
}

// ---------------------------------------------------------------------------
// Host side
// ---------------------------------------------------------------------------
typedef CUresult (*PFN_tmencode)(CUtensorMap*, CUtensorMapDataType, cuuint32_t,
                                 void*, const cuuint64_t*, const cuuint64_t*,
                                 const cuuint32_t*, const cuuint32_t*,
                                 CUtensorMapInterleave, CUtensorMapSwizzle,
                                 CUtensorMapL2promotion, CUtensorMapFloatOOBfill);

static PFN_tmencode get_encoder() {
    void* fn = nullptr;
    cudaDriverEntryPointQueryResult st;
#if CUDART_VERSION >= 12050
    if (cudaGetDriverEntryPointByVersion("cuTensorMapEncodeTiled", &fn, 12000,
                                         cudaEnableDefault, &st) != cudaSuccess)
        fn = nullptr;
#else
    if (cudaGetDriverEntryPoint("cuTensorMapEncodeTiled", &fn,
                                cudaEnableDefault, &st) != cudaSuccess)
        fn = nullptr;
#endif
    if (st != cudaDriverEntryPointSuccess) fn = nullptr;
    return (PFN_tmencode)fn;
}

static bool enc2d(PFN_tmencode f, CUtensorMap* m, void* p,
                  uint64_t d0, uint64_t d1, uint64_t strideBytes) {
    cuuint64_t dims[2] = {(cuuint64_t)d0, (cuuint64_t)d1};
    cuuint64_t str[1]  = {(cuuint64_t)strideBytes};
    cuuint32_t box[2]  = {64, 128};   // 64 halves = 128B rows (SW128)
    cuuint32_t es[2]   = {1, 1};
    return f(m, CU_TENSOR_MAP_DATA_TYPE_UINT16, 2, p, dims, str, box, es,
             CU_TENSOR_MAP_INTERLEAVE_NONE, CU_TENSOR_MAP_SWIZZLE_128B,
             CU_TENSOR_MAP_L2_PROMOTION_L2_128B,
             CU_TENSOR_MAP_FLOAT_OOB_FILL_NONE) == CUDA_SUCCESS;
}

extern "C" void kernel_launch(void* const* d_in, const int* in_sizes, int n_in,
                              void* d_out, int out_size)
{
    const float* x          = (const float*)d_in[0];
    const float* in_proj_w  = (const float*)d_in[1];
    const float* conv_w     = (const float*)d_in[2];
    const float* conv_b     = (const float*)d_in[3];
    const float* x_proj_w   = (const float*)d_in[4];
    const float* dt_proj_w  = (const float*)d_in[5];
    const float* dt_proj_b  = (const float*)d_in[6];
    const float* A_log      = (const float*)d_in[7];
    const float* Dp         = (const float*)d_in[8];
    const float* out_proj_w = (const float*)d_in[9];
    float* out = (float*)d_out;

    float *xdbl, *xp4, *hp, *hs, *Ss;
    __half *xzh, *uh, *dtin_h, *dth, *yh, *xh, *w1h, *w2h, *w3h, *w4h;
    cudaGetSymbolAddress((void**)&xzh,    g_xzh);
    cudaGetSymbolAddress((void**)&uh,     g_uh);
    cudaGetSymbolAddress((void**)&xdbl,   g_xdbl);
    cudaGetSymbolAddress((void**)&xp4,    g_xp4);
    cudaGetSymbolAddress((void**)&dtin_h, g_dtin_h);
    cudaGetSymbolAddress((void**)&dth,    g_dth);
    cudaGetSymbolAddress((void**)&yh,     g_yh);
    cudaGetSymbolAddress((void**)&xh,     g_xh);
    cudaGetSymbolAddress((void**)&w1h,    g_w1h);
    cudaGetSymbolAddress((void**)&w2h,    g_w2h);
    cudaGetSymbolAddress((void**)&w3h,    g_w3h);
    cudaGetSymbolAddress((void**)&w4h,    g_w4h);
    cudaGetSymbolAddress((void**)&hp,     g_hpart);
    cudaGetSymbolAddress((void**)&hs,     g_hstart);
    cudaGetSymbolAddress((void**)&Ss,     g_S);

    // TMA tensor maps (host-only, encoded at capture time)
    PFN_tmencode enc = get_encoder();
    CUtensorMap tmXA, tmW1, tmUA, tmW2, tmDA, tmW3, tmYA, tmW4;
    bool use_tma = (enc != nullptr);
    if (use_tma) {
        use_tma = use_tma && enc2d(enc, &tmXA, xh,     DMODEL, ROWS,      DMODEL * 2);
        use_tma = use_tma && enc2d(enc, &tmW1, w1h,    DMODEL, 2*DINNER,  DMODEL * 2);
        use_tma = use_tma && enc2d(enc, &tmUA, uh,     DINNER, ROWS,      DINNER * 2);
        use_tma = use_tma && enc2d(enc, &tmW2, w2h,    DINNER, XPROJ_N,   DINNER * 2);
        use_tma = use_tma && enc2d(enc, &tmDA, dtin_h, DTRANK, ROWS,      DTRANK * 2);
        use_tma = use_tma && enc2d(enc, &tmW3, w3h,    DTRANK, DINNER,    DTRANK * 2);
        use_tma = use_tma && enc2d(enc, &tmYA, yh,     DINNER, ROWS,      DINNER * 2);
        use_tma = use_tma && enc2d(enc, &tmW4, w4h,    DINNER, DMODEL,    DINNER * 2);
    }

    if (use_tma) {
        cudaFuncSetAttribute(tma_hgemm<0>, cudaFuncAttributeMaxDynamicSharedMemorySize, TSMEM_BYTES);
        cudaFuncSetAttribute(tma_hgemm<3>, cudaFuncAttributeMaxDynamicSharedMemorySize, TSMEM_BYTES);
        cudaFuncSetAttribute(tma_hgemm<4>, cudaFuncAttributeMaxDynamicSharedMemorySize, TSMEM_BYTES);
        cudaFuncSetAttribute(tma_hgemm<5>, cudaFuncAttributeMaxDynamicSharedMemorySize, TSMEM_BYTES);
    } else {
        cudaFuncSetAttribute(hgemm_nt<0>, cudaFuncAttributeMaxDynamicSharedMemorySize, HSMEM_BYTES);
        cudaFuncSetAttribute(hgemm_nt<3>, cudaFuncAttributeMaxDynamicSharedMemorySize, HSMEM_BYTES);
        cudaFuncSetAttribute(hgemm_nt<4>, cudaFuncAttributeMaxDynamicSharedMemorySize, HSMEM_BYTES);
        cudaFuncSetAttribute(hgemm_nt<5>, cudaFuncAttributeMaxDynamicSharedMemorySize, HSMEM_BYTES);
    }

    // 0) fused fp16 conversion of x + all weights (one launch)
    cvt_all_kernel<<<(NG_TOT + 255) / 256, 256>>>(x, xh, in_proj_w, w1h,
                                                  x_proj_w, w2h, dt_proj_w, w3h,
                                                  out_proj_w, w4h);

    // 1) xz = x @ in_proj_w^T -> fp16 [4096, 4096]
    if (use_tma)
        tma_hgemm<3><<<dim3(32, 32), 256, TSMEM_BYTES>>>(tmXA, tmW1, nullptr, nullptr, xzh,
                                           ROWS, 2 * DINNER, DMODEL, 2 * DINNER);
    else
        hgemm_nt<3><<<dim3(32, 32), 256, HSMEM_BYTES>>>(xh, w1h, nullptr, nullptr, xzh,
                                           ROWS, 2 * DINNER, DMODEL,
                                           DMODEL, DMODEL, 2 * DINNER);
    // 2) u = silu(causal_conv(xb) + b)   [4096, 2048]  (fp16)
    conv_silu_kernel<<<(ROWS * DINNER) / 256, 256>>>(xzh, conv_w, conv_b, uh);
    // 3) x_dbl = u @ x_proj_w^T          [4096, 160]  split-K x4 + reduce
    if (use_tma)
        tma_hgemm<4><<<dim3(2, 32, KSPLIT), 256, TSMEM_BYTES>>>(tmUA, tmW2, xp4, nullptr, nullptr,
                                           ROWS, XPROJ_N, DINNER / KSPLIT, XPROJ_N);
    else
        hgemm_nt<4><<<dim3(2, 32, KSPLIT), 256, HSMEM_BYTES>>>(uh, w2h, xp4, nullptr, nullptr,
                                           ROWS, XPROJ_N, DINNER / KSPLIT,
                                           DINNER, DINNER, XPROJ_N);
    xproj_reduce<<<(XPN / 4 + 255) / 256, 256>>>(xp4, xdbl, dtin_h);
    // 4) dt = softplus(dt_in @ dt_proj_w^T + b) -> fp16  [4096, 2048]
    if (use_tma)
        tma_hgemm<5><<<dim3(16, 32), 256, TSMEM_BYTES>>>(tmDA, tmW3, nullptr, dt_proj_b, dth,
                                           ROWS, DINNER, DTRANK, DINNER);
    else
        hgemm_nt<5><<<dim3(16, 32), 256, HSMEM_BYTES>>>(dtin_h, w3h, nullptr, dt_proj_b, dth,
                                           ROWS, DINNER, DTRANK,
                                           DTRANK, DTRANK, DINNER);
    // 5) chunked selective scan -> y (fp16)
    scan_pass1<<<dim3(DINNER / 128, CHUNKS, BATCH), 128>>>(uh, dth, xdbl, A_log, hp, Ss);
    scan_combine<<<dim3(DINNER / 128, DSTATE, BATCH), 128>>>(A_log, Ss, hp, hs);
    scan_pass2<<<dim3(DINNER / 128, CHUNKS, BATCH), 128>>>(uh, dth, xdbl, xzh, A_log, Dp, hs, yh);
    // 6) out = y @ out_proj_w^T          [4096, 1024]
    if (use_tma)
        tma_hgemm<0><<<dim3(8, 32), 256, TSMEM_BYTES>>>(tmYA, tmW4, out, nullptr, nullptr,
                                           ROWS, DMODEL, DINNER, DMODEL);
    else
        hgemm_nt<0><<<dim3(8, 32), 256, HSMEM_BYTES>>>(yh, w4h, out, nullptr, nullptr,
                                           ROWS, DMODEL, DINNER,
                                           DINNER, DINNER, DMODEL);
}

// round 17
// speedup vs baseline: 1.4999x; 1.4999x over previous
#include <cuda_runtime.h>
#include <cuda.h>
#include <cuda_fp16.h>
#include <math.h>
#include <stdint.h>

// Problem constants
#define BATCH 2
#define LSEQ 2048
#define DMODEL 1024
#define DINNER 2048
#define DSTATE 16
#define DTRANK 128
#define ROWS (BATCH * LSEQ)           // 4096
#define XPROJ_N (DTRANK + 2 * DSTATE) // 160
#define CHUNKS 32
#define CLEN (LSEQ / CHUNKS)          // 64
#define KSPLIT 4
#define XPN (ROWS * XPROJ_N)          // 655360

// Scratch (device globals: allocation-free rule)
__device__ __half g_xzh[(size_t)ROWS * (2 * DINNER)];
__device__ __half g_uh[(size_t)ROWS * DINNER];
__device__ float  g_xdbl[(size_t)ROWS * XPROJ_N];
__device__ float  g_xp4[(size_t)KSPLIT * XPN];
__device__ __half g_dtin_h[(size_t)ROWS * DTRANK];
__device__ __half g_dth[(size_t)ROWS * DINNER];
__device__ __half g_yh[(size_t)ROWS * DINNER];
__device__ __half g_xh[(size_t)ROWS * DMODEL];
__device__ __half g_w1h[(size_t)(2 * DINNER) * DMODEL];
__device__ __half g_w2h[(size_t)XPROJ_N * DINNER];
__device__ __half g_w3h[(size_t)DINNER * DTRANK];
__device__ __half g_w4h[(size_t)DMODEL * DINNER];
__device__ float  g_hpart[(size_t)BATCH * CHUNKS * DSTATE * DINNER];
__device__ float  g_hstart[(size_t)BATCH * CHUNKS * DSTATE * DINNER];
__device__ float  g_S[(size_t)BATCH * CHUNKS * DINNER];

// ---------------------------------------------------------------------------
// helpers
// ---------------------------------------------------------------------------
__device__ __forceinline__ void cp_async16(uint32_t saddr, const void* g) {
    asm volatile("cp.async.cg.shared.global [%0], [%1], 16;\n" :: "r"(saddr), "l"(g));
}
__device__ __forceinline__ void cp_async16_zfill(uint32_t saddr, const void* g, bool pred) {
    int sz = pred ? 16 : 0;
    asm volatile("cp.async.cg.shared.global [%0], [%1], 16, %2;\n" :: "r"(saddr), "l"(g), "r"(sz));
}
__device__ __forceinline__ void ldsm_x4(uint32_t& r0, uint32_t& r1, uint32_t& r2,
                                        uint32_t& r3, uint32_t addr) {
    asm volatile("ldmatrix.sync.aligned.m8n8.x4.shared.b16 {%0,%1,%2,%3}, [%4];"
                 : "=r"(r0), "=r"(r1), "=r"(r2), "=r"(r3) : "r"(addr));
}

#define MBARRIER_INIT(mbar, count) \
    asm volatile("mbarrier.init.shared.b64 [%0], %1;" :: "r"((uint32_t)(mbar)), "r"((uint32_t)(count)) : "memory")
#define MBARRIER_EXPECT_TX(mbar, tx) \
    asm volatile("mbarrier.arrive.expect_tx.shared.b64 _, [%0], %1;" :: "r"((uint32_t)(mbar)), "r"((uint32_t)(tx)) : "memory")
#define MBARRIER_WAIT_PARITY(mbar_smem_addr, phase_parity) do { \
    uint32_t _mbar = (uint32_t)(mbar_smem_addr); \
    uint32_t _parity = (uint32_t)(phase_parity); \
    uint32_t _done; \
    asm volatile("{\n\t.reg .pred p;\n\t" \
        "mbarrier.try_wait.parity.acquire.cta.shared::cta.b64 p, [%1], %2;\n\t" \
        "selp.b32 %0, 1, 0, p;\n\t}" \
        : "=r"(_done) : "r"(_mbar), "r"(_parity) : "memory"); \
    if (!_done) { \
        asm volatile("{\n\t.reg .pred P1;\n\t" \
            "WAIT_LOOP_%=:\n\t" \
            "mbarrier.try_wait.parity.acquire.cta.shared::cta.b64 P1, [%0], %1, 0x989680;\n\t" \
            "@P1 bra.uni WAIT_DONE_%=;\n\t" \
            "bra.uni WAIT_LOOP_%=;\n\t" \
            "WAIT_DONE_%=:\n\t}" \
            :: "r"(_mbar), "r"(_parity) : "memory"); \
    } \
} while(0)

__device__ __forceinline__ void tma_load_2d(uint32_t smem_addr, const CUtensorMap* map,
                                            int cx, int cy, uint32_t mbar) {
    asm volatile(
        "cp.async.bulk.tensor.2d.shared::cta.global.tile.mbarrier::complete_tx::bytes "
        "[%0], [%1, {%2, %3}], [%4];"
        :: "r"(smem_addr), "l"(map), "r"(cx), "r"(cy), "r"(mbar) : "memory");
}

// ===========================================================================
// TMA-fed fp16 GEMM (R14 proven config): C[M,N] = epi( A[M,K] @ B[N,K]^T ),
// BM=BN=128, BK=64, 3 stages, SW128 tiles (128B rows), TMA by thread 0,
// ring pipeline with per-iter __syncthreads. Tile bases 1024B-aligned.
// De-swizzle: xorv=(lane&7)<<4 (row&7==lane&7 for every fragment).
// EPI: 0 fp32 C; 3 fp16 Ch; 4 split-K fp32 partial; 5 softplus+bias fp16 Ch.
// ===========================================================================
#define TSTG 3
#define T_TILE 16384                    // 128 rows x 128B
#define T_STAGE (2 * T_TILE)            // A + B = 32768
#define TSMEM_BYTES (2048 + TSTG * T_STAGE)   // 100352 (incl. align slack)

template <int EPI>
__global__ __launch_bounds__(256, 2) void tma_hgemm(
    const __grid_constant__ CUtensorMap tmA,
    const __grid_constant__ CUtensorMap tmB,
    float* __restrict__ C, const float* __restrict__ bias,
    __half* __restrict__ Ch,
    int M, int N, int K, int ldc)
{
    extern __shared__ __align__(1024) char tsm[];
    const uint32_t sb = (uint32_t)__cvta_generic_to_shared(tsm);
    const int tid  = threadIdx.x;
    const int wid  = tid >> 5;
    const int lane = tid & 31;
    const int g    = lane >> 2;
    const int tg   = lane & 3;
    const int m0 = blockIdx.y * 128;
    const int n0 = blockIdx.x * 128;
    const int wm = (wid >> 2) * 64;
    const int wn = (wid & 3) * 32;
    const int kbase = blockIdx.z * K;
    const int nk = K / 64;

    const int lrow8 = ((lane >> 3) & 1) * 8 + (lane & 7);     // 0..15
    const uint32_t c16  = (uint32_t)((lane >> 4) * 16);       // 0 or 16
    const uint32_t xorv = (uint32_t)((lane & 7) << 4);        // SW128 de-swizzle
    const uint32_t stage0 = (sb + 64 + 1023) & ~1023u;        // 1024B-aligned!
    const uint32_t aLane = (uint32_t)((wm + lrow8) * 128);
    const uint32_t bLane = (uint32_t)((wn + lrow8) * 128);

    if (tid == 0) {
#pragma unroll
        for (int s = 0; s < TSTG; s++) MBARRIER_INIT(sb + 8 * s, 1);
    }
    __syncthreads();

    // prologue: fill ALL stages
    if (tid == 0) {
#pragma unroll
        for (int t = 0; t < TSTG; t++) {
            if (t < nk) {
                uint32_t bar = sb + 8 * t;
                uint32_t da = stage0 + t * T_STAGE;
                MBARRIER_EXPECT_TX(bar, T_STAGE);
                tma_load_2d(da, &tmA, kbase + t * 64, m0, bar);
                tma_load_2d(da + T_TILE, &tmB, kbase + t * 64, n0, bar);
            }
        }
    }

    float acc[4][4][4];
#pragma unroll
    for (int i = 0; i < 4; i++)
#pragma unroll
        for (int j = 0; j < 4; j++)
#pragma unroll
            for (int r = 0; r < 4; r++) acc[i][j][r] = 0.f;

    int s = 0, ph = 0;
    for (int t = 0; t < nk; t++) {
        MBARRIER_WAIT_PARITY(sb + 8 * s, ph);
        const uint32_t aS = stage0 + s * T_STAGE;
        const uint32_t bS = aS + T_TILE;
#pragma unroll
        for (int ks = 0; ks < 4; ks++) {
            const uint32_t col = ((uint32_t)(ks * 32) + c16) ^ xorv;
            uint32_t af[4][4];
#pragma unroll
            for (int mi = 0; mi < 4; mi++)
                ldsm_x4(af[mi][0], af[mi][1], af[mi][2], af[mi][3],
                        aS + aLane + mi * 2048 + col);
            uint32_t bf[4][2];
#pragma unroll
            for (int n2 = 0; n2 < 2; n2++) {
                uint32_t b0, b1, b2, b3;
                ldsm_x4(b0, b1, b2, b3, bS + bLane + n2 * 2048 + col);
                bf[2 * n2][0] = b0; bf[2 * n2 + 1][0] = b1;
                bf[2 * n2][1] = b2; bf[2 * n2 + 1][1] = b3;
            }
#pragma unroll
            for (int mi = 0; mi < 4; mi++)
#pragma unroll
                for (int ni = 0; ni < 4; ni++) {
                    asm volatile(
                        "mma.sync.aligned.m16n8k16.row.col.f32.f16.f16.f32 "
                        "{%0,%1,%2,%3}, {%4,%5,%6,%7}, {%8,%9}, {%0,%1,%2,%3};"
                        : "+f"(acc[mi][ni][0]), "+f"(acc[mi][ni][1]),
                          "+f"(acc[mi][ni][2]), "+f"(acc[mi][ni][3])
                        : "r"(af[mi][0]), "r"(af[mi][1]), "r"(af[mi][2]), "r"(af[mi][3]),
                          "r"(bf[ni][0]), "r"(bf[ni][1]));
                }
        }
        __syncthreads();               // all warps done with stage s
        if (tid == 0 && t + TSTG < nk) {
            uint32_t bar = sb + 8 * s;
            MBARRIER_EXPECT_TX(bar, T_STAGE);
            tma_load_2d(aS, &tmA, kbase + (t + TSTG) * 64, m0, bar);
            tma_load_2d(bS, &tmB, kbase + (t + TSTG) * 64, n0, bar);
        }
        if (++s == TSTG) { s = 0; ph ^= 1; }
    }

    float* Cw = C;
    if (EPI == 4) Cw = C + (size_t)blockIdx.z * M * ldc;

#pragma unroll
    for (int mi = 0; mi < 4; mi++) {
        int r0 = m0 + wm + mi * 16 + g;
#pragma unroll
        for (int ni = 0; ni < 4; ni++) {
            int c0 = n0 + wn + ni * 8 + 2 * tg;
            if (c0 >= N) continue;
#pragma unroll
            for (int hh = 0; hh < 2; hh++) {
                int row = r0 + hh * 8;
                float v0 = acc[mi][ni][hh * 2 + 0];
                float v1 = acc[mi][ni][hh * 2 + 1];
                if (EPI == 5) {
                    v0 += bias[c0];     v1 += bias[c0 + 1];
                    v0 = (v0 > 20.f) ? v0 : log1pf(__expf(v0));
                    v1 = (v1 > 20.f) ? v1 : log1pf(__expf(v1));
                    *(__half2*)(Ch + (size_t)row * ldc + c0) = __floats2half2_rn(v0, v1);
                } else if (EPI == 3) {
                    *(__half2*)(Ch + (size_t)row * ldc + c0) = __floats2half2_rn(v0, v1);
                } else {
                    *(float2*)(Cw + (size_t)row * ldc + c0) = make_float2(v0, v1);
                }
            }
        }
    }
}

// ===========================================================================
// Fallback fp16 GEMM (R9 config, proven): cp.async 4-stage, BK=32, LDH=40.
// ===========================================================================
#define BKH 32
#define PADH 8
#define LDH (BKH + PADH)
#define NSTG 4
#define HSMEM_BYTES (2 * NSTG * 128 * LDH * 2)   // 81920

template <int EPI>
__global__ __launch_bounds__(256, 2) void hgemm_nt(
    const __half* __restrict__ A, const __half* __restrict__ B,
    float* __restrict__ C, const float* __restrict__ bias,
    __half* __restrict__ Ch,
    int M, int N, int K, int lda, int ldb, int ldc)
{
    extern __shared__ __half sh[];
    __half (*As)[128][LDH] = (__half(*)[128][LDH])sh;
    __half (*Bs)[128][LDH] = (__half(*)[128][LDH])(sh + NSTG * 128 * LDH);

    const int tid  = threadIdx.x;
    const int wid  = tid >> 5;
    const int lane = tid & 31;
    const int g    = lane >> 2;
    const int tg   = lane & 3;
    const int m0 = blockIdx.y * 128;
    const int n0 = blockIdx.x * 128;
    const int wm = (wid >> 2) * 64;
    const int wn = (wid & 3) * 32;

    const int kbase = blockIdx.z * K;
    A += kbase;
    B += kbase;

    const int lrow8 = ((lane >> 3) & 1) * 8 + (lane & 7);
    const int lcol8 = (lane >> 4) * 8;
    const uint32_t aBase = (uint32_t)__cvta_generic_to_shared(&As[0][wm + lrow8][lcol8]);
    const uint32_t bBase = (uint32_t)__cvta_generic_to_shared(&Bs[0][wn + lrow8][lcol8]);
    const uint32_t STG_STRIDE = 128 * LDH * 2;
    const uint32_t ROW16 = 16 * LDH * 2;

    float acc[4][4][4];
#pragma unroll
    for (int i = 0; i < 4; i++)
#pragma unroll
        for (int j = 0; j < 4; j++)
#pragma unroll
            for (int r = 0; r < 4; r++) acc[i][j][r] = 0.f;

    auto load_tiles = [&](int s, int k0) {
#pragma unroll
        for (int h = 0; h < 2; h++) {
            int idx = tid + h * 256;
            int row = idx >> 2;
            int ch  = idx & 3;
            uint32_t da = (uint32_t)__cvta_generic_to_shared(&As[s][row][ch * 8]);
            cp_async16(da, A + (size_t)(m0 + row) * lda + k0 + ch * 8);
            uint32_t db = (uint32_t)__cvta_generic_to_shared(&Bs[s][row][ch * 8]);
            int brow = n0 + row;
            const __half* src = B + (size_t)(brow < N ? brow : 0) * ldb + k0 + ch * 8;
            cp_async16_zfill(db, src, brow < N);
        }
    };

    const int nk = K / BKH;
#pragma unroll
    for (int t = 0; t < NSTG - 1; t++) {
        if (t < nk) load_tiles(t, t * BKH);
        asm volatile("cp.async.commit_group;\n" ::: "memory");
    }

    for (int t = 0; t < nk; t++) {
        const int s = t % NSTG;
        asm volatile("cp.async.wait_group %0;\n" :: "n"(NSTG - 2) : "memory");
        __syncthreads();
        if (t + NSTG - 1 < nk) load_tiles((t + NSTG - 1) % NSTG, (t + NSTG - 1) * BKH);
        asm volatile("cp.async.commit_group;\n" ::: "memory");

        const uint32_t aS = aBase + s * STG_STRIDE;
        const uint32_t bS = bBase + s * STG_STRIDE;
#pragma unroll
        for (int ks = 0; ks < 2; ks++) {
            const uint32_t kkb = ks * 32;
            uint32_t af[4][4];
#pragma unroll
            for (int mi = 0; mi < 4; mi++)
                ldsm_x4(af[mi][0], af[mi][1], af[mi][2], af[mi][3],
                        aS + mi * ROW16 + kkb);
            uint32_t bf[4][2];
#pragma unroll
            for (int n2 = 0; n2 < 2; n2++) {
                uint32_t b0, b1, b2, b3;
                ldsm_x4(b0, b1, b2, b3, bS + n2 * ROW16 + kkb);
                bf[2 * n2][0] = b0; bf[2 * n2 + 1][0] = b1;
                bf[2 * n2][1] = b2; bf[2 * n2 + 1][1] = b3;
            }
#pragma unroll
            for (int mi = 0; mi < 4; mi++)
#pragma unroll
                for (int ni = 0; ni < 4; ni++) {
                    asm volatile(
                        "mma.sync.aligned.m16n8k16.row.col.f32.f16.f16.f32 "
                        "{%0,%1,%2,%3}, {%4,%5,%6,%7}, {%8,%9}, {%0,%1,%2,%3};"
                        : "+f"(acc[mi][ni][0]), "+f"(acc[mi][ni][1]),
                          "+f"(acc[mi][ni][2]), "+f"(acc[mi][ni][3])
                        : "r"(af[mi][0]), "r"(af[mi][1]), "r"(af[mi][2]), "r"(af[mi][3]),
                          "r"(bf[ni][0]), "r"(bf[ni][1]));
                }
        }
    }

    float* Cw = C;
    if (EPI == 4) Cw = C + (size_t)blockIdx.z * M * ldc;

#pragma unroll
    for (int mi = 0; mi < 4; mi++) {
        int r0 = m0 + wm + mi * 16 + g;
#pragma unroll
        for (int ni = 0; ni < 4; ni++) {
            int c0 = n0 + wn + ni * 8 + 2 * tg;
            if (c0 >= N) continue;
#pragma unroll
            for (int hh = 0; hh < 2; hh++) {
                int row = r0 + hh * 8;
                float v0 = acc[mi][ni][hh * 2 + 0];
                float v1 = acc[mi][ni][hh * 2 + 1];
                if (EPI == 5) {
                    v0 += bias[c0];     v1 += bias[c0 + 1];
                    v0 = (v0 > 20.f) ? v0 : log1pf(__expf(v0));
                    v1 = (v1 > 20.f) ? v1 : log1pf(__expf(v1));
                    *(__half2*)(Ch + (size_t)row * ldc + c0) = __floats2half2_rn(v0, v1);
                } else if (EPI == 3) {
                    *(__half2*)(Ch + (size_t)row * ldc + c0) = __floats2half2_rn(v0, v1);
                } else {
                    *(float2*)(Cw + (size_t)row * ldc + c0) = make_float2(v0, v1);
                }
            }
        }
    }
}

// ---------------------------------------------------------------------------
// x_proj split-K reduce: xdbl = sum of 4 partials; dtin_h = fp16 of cols<128
// ---------------------------------------------------------------------------
__global__ __launch_bounds__(256) void xproj_reduce(
    const float* __restrict__ part, float* __restrict__ xdbl,
    __half* __restrict__ dtin)
{
    int i = blockIdx.x * blockDim.x + threadIdx.x;
    if (i >= XPN / 4) return;
    const float4* p = (const float4*)part;
    float4 v = p[i];
    float4 a = p[i + XPN / 4];
    float4 b = p[i + 2 * (XPN / 4)];
    float4 c = p[i + 3 * (XPN / 4)];
    v.x += a.x + b.x + c.x;
    v.y += a.y + b.y + c.y;
    v.z += a.z + b.z + c.z;
    v.w += a.w + b.w + c.w;
    ((float4*)xdbl)[i] = v;
    int col4 = (i % (XPROJ_N / 4)) * 4;
    if (col4 < DTRANK) {
        int row = i / (XPROJ_N / 4);
        __half2 h[2] = { __floats2half2_rn(v.x, v.y), __floats2half2_rn(v.z, v.w) };
        *(uint2*)(dtin + (size_t)row * DTRANK + col4) = *(uint2*)h;
    }
}

// ---------------------------------------------------------------------------
// fused fp32 -> fp16 conversion of x + 4 weight matrices (one launch)
// ---------------------------------------------------------------------------
#define NG_X  (ROWS * DMODEL / 8)
#define NG_W1 (2 * DINNER * DMODEL / 8)
#define NG_W2 (XPROJ_N * DINNER / 8)
#define NG_W3 (DINNER * DTRANK / 8)
#define NG_W4 (DMODEL * DINNER / 8)
#define NG_TOT (NG_X + NG_W1 + NG_W2 + NG_W3 + NG_W4)

__device__ __forceinline__ void cvt8(const float* in, __half* out, int i) {
    const float4* p = (const float4*)in + (size_t)i * 2;
    float4 a = p[0], b = p[1];
    __half2 h[4];
    h[0] = __floats2half2_rn(a.x, a.y);
    h[1] = __floats2half2_rn(a.z, a.w);
    h[2] = __floats2half2_rn(b.x, b.y);
    h[3] = __floats2half2_rn(b.z, b.w);
    ((uint4*)out)[i] = *(uint4*)h;
}

__global__ __launch_bounds__(256) void cvt_all_kernel(
    const float* __restrict__ x,  __half* __restrict__ xh,
    const float* __restrict__ w1, __half* __restrict__ w1h,
    const float* __restrict__ w2, __half* __restrict__ w2h,
    const float* __restrict__ w3, __half* __restrict__ w3h,
    const float* __restrict__ w4, __half* __restrict__ w4h)
{
    int i = blockIdx.x * blockDim.x + threadIdx.x;
    if (i < NG_X)                           { cvt8(x, xh, i); return; }
    i -= NG_X;
    if (i < NG_W1)                          { cvt8(w1, w1h, i); return; }
    i -= NG_W1;
    if (i < NG_W2)                          { cvt8(w2, w2h, i); return; }
    i -= NG_W2;
    if (i < NG_W3)                          { cvt8(w3, w3h, i); return; }
    i -= NG_W3;
    if (i < NG_W4)                          { cvt8(w4, w4h, i); }
}

// ---------------------------------------------------------------------------
// Causal depthwise conv1d (d_conv=4) + bias + SiLU -> u_h.
// 2 adjacent channels per thread: uint32 tap loads (fully coalesced),
// 2x float4 weight loads, float2 bias, half2 store.
// ---------------------------------------------------------------------------
__global__ __launch_bounds__(256) void conv_silu_kernel(
    const __half* __restrict__ xzh, const float* __restrict__ w,
    const float* __restrict__ bias, __half* __restrict__ uh)
{
    int idx = blockIdx.x * blockDim.x + threadIdx.x;   // pair index
    if (idx >= ROWS * DINNER / 2) return;
    int dp = idx & (DINNER / 2 - 1);     // pair within row
    int d = dp * 2;
    int row = idx >> 10;
    int l = row & (LSEQ - 1);

    float4 wa = *(const float4*)(w + d * 4);        // taps for channel d
    float4 wb = *(const float4*)(w + d * 4 + 4);    // taps for channel d+1
    float2 bs = *(const float2*)(bias + d);

    const __half* base = xzh + (size_t)row * (2 * DINNER) + d;
    float2 t0, t1, t2, t3;
    { __half2 v = *(const __half2*)(base); t3 = __half22float2(v); }
    float a0 = fmaf(wa.w, t3.x, bs.x);
    float a1 = fmaf(wb.w, t3.y, bs.y);
    if (l >= 1) { __half2 v = *(const __half2*)(base - (2 * DINNER));
                  t2 = __half22float2(v);
                  a0 = fmaf(wa.z, t2.x, a0); a1 = fmaf(wb.z, t2.y, a1); }
    if (l >= 2) { __half2 v = *(const __half2*)(base - 2 * (2 * DINNER));
                  t1 = __half22float2(v);
                  a0 = fmaf(wa.y, t1.x, a0); a1 = fmaf(wb.y, t1.y, a1); }
    if (l >= 3) { __half2 v = *(const __half2*)(base - 3 * (2 * DINNER));
                  t0 = __half22float2(v);
                  a0 = fmaf(wa.x, t0.x, a0); a1 = fmaf(wb.x, t0.y, a1); }
    float s0 = a0 / (1.f + __expf(-a0));
    float s1 = a1 / (1.f + __expf(-a1));
    *(__half2*)(uh + (size_t)row * DINNER + d) = __floats2half2_rn(s0, s1);
}

// ---------------------------------------------------------------------------
// Chunked selective scan (exact chunk decomposition via exp(A * sum dt)).
// ---------------------------------------------------------------------------
__device__ __forceinline__ void load_bc16(const float* __restrict__ p, float* v) {
    float4 a = ((const float4*)p)[0], b2 = ((const float4*)p)[1];
    float4 c = ((const float4*)p)[2], e = ((const float4*)p)[3];
    v[0]=a.x; v[1]=a.y; v[2]=a.z; v[3]=a.w;
    v[4]=b2.x; v[5]=b2.y; v[6]=b2.z; v[7]=b2.w;
    v[8]=c.x; v[9]=c.y; v[10]=c.z; v[11]=c.w;
    v[12]=e.x; v[13]=e.y; v[14]=e.z; v[15]=e.w;
}

__global__ __launch_bounds__(128) void scan_pass1(
    const __half* __restrict__ uh, const __half* __restrict__ dth,
    const float* __restrict__ xdbl, const float* __restrict__ A_log,
    float* __restrict__ hpart, float* __restrict__ Ssum)
{
    const int d = blockIdx.x * 128 + threadIdx.x;
    const int c = blockIdx.y;
    const int b = blockIdx.z;

    float A[DSTATE];
    const float a0 = -__expf(A_log[d * DSTATE]);
    bool structured = true;
#pragma unroll
    for (int n = 0; n < DSTATE; n++) {
        A[n] = -__expf(A_log[d * DSTATE + n]);
        structured = structured &&
            (fabsf(A[n] - (float)(n + 1) * a0) <= 1e-4f * (float)(n + 1));
    }

    float h[DSTATE];
#pragma unroll
    for (int n = 0; n < DSTATE; n++) h[n] = 0.f;
    float S = 0.f;

    const int l0 = c * CLEN;
    if (structured) {
        for (int l = l0; l < l0 + CLEN; l++) {
            const size_t row = (size_t)b * LSEQ + l;
            const float ut  = __half2float(uh[row * DINNER + d]);
            const float dtt = __half2float(dth[row * DINNER + d]);
            float Bv[16];
            load_bc16(xdbl + row * XPROJ_N + DTRANK, Bv);
            S += dtt;
            const float dtu = dtt * ut;
            const float E = __expf(dtt * a0);
            float dA = E;
#pragma unroll
            for (int n = 0; n < DSTATE; n++) {
                h[n] = fmaf(dA, h[n], dtu * Bv[n]);
                dA *= E;
            }
        }
    } else {
        for (int l = l0; l < l0 + CLEN; l++) {
            const size_t row = (size_t)b * LSEQ + l;
            const float ut  = __half2float(uh[row * DINNER + d]);
            const float dtt = __half2float(dth[row * DINNER + d]);
            float Bv[16];
            load_bc16(xdbl + row * XPROJ_N + DTRANK, Bv);
            S += dtt;
            const float dtu = dtt * ut;
#pragma unroll
            for (int n = 0; n < DSTATE; n++)
                h[n] = fmaf(__expf(dtt * A[n]), h[n], dtu * Bv[n]);
        }
    }

    const size_t base = ((size_t)(b * CHUNKS + c) * DSTATE) * DINNER + d;
#pragma unroll
    for (int n = 0; n < DSTATE; n++) hpart[base + (size_t)n * DINNER] = h[n];
    Ssum[(size_t)(b * CHUNKS + c) * DINNER + d] = S;
}

__global__ __launch_bounds__(128) void scan_combine(
    const float* __restrict__ A_log, const float* __restrict__ Ssum,
    const float* __restrict__ hpart, float* __restrict__ hstart)
{
    const int d = blockIdx.x * 128 + threadIdx.x;
    const int n = blockIdx.y;
    const int b = blockIdx.z;
    const float An = -__expf(A_log[d * DSTATE + n]);
    float h = 0.f;
    for (int c = 0; c < CHUNKS; c++) {
        const size_t idx = ((size_t)(b * CHUNKS + c) * DSTATE + n) * DINNER + d;
        hstart[idx] = h;
        const float P = __expf(An * Ssum[(size_t)(b * CHUNKS + c) * DINNER + d]);
        h = fmaf(P, h, hpart[idx]);
    }
}

__global__ __launch_bounds__(128) void scan_pass2(
    const __half* __restrict__ uh, const __half* __restrict__ dth,
    const float* __restrict__ xdbl, const __half* __restrict__ xzh,
    const float* __restrict__ A_log, const float* __restrict__ Dp,
    const float* __restrict__ hstart, __half* __restrict__ yh)
{
    const int d = blockIdx.x * 128 + threadIdx.x;
    const int c = blockIdx.y;
    const int b = blockIdx.z;

    float A[DSTATE];
    const float a0 = -__expf(A_log[d * DSTATE]);
    bool structured = true;
#pragma unroll
    for (int n = 0; n < DSTATE; n++) {
        A[n] = -__expf(A_log[d * DSTATE + n]);
        structured = structured &&
            (fabsf(A[n] - (float)(n + 1) * a0) <= 1e-4f * (float)(n + 1));
    }
    const float Dd = Dp[d];

    float h[DSTATE];
    const size_t hbase = ((size_t)(b * CHUNKS + c) * DSTATE) * DINNER + d;
#pragma unroll
    for (int n = 0; n < DSTATE; n++) h[n] = hstart[hbase + (size_t)n * DINNER];

    const int l0 = c * CLEN;
    if (structured) {
        for (int l = l0; l < l0 + CLEN; l++) {
            const size_t row = (size_t)b * LSEQ + l;
            const float ut  = __half2float(uh[row * DINNER + d]);
            const float dtt = __half2float(dth[row * DINNER + d]);
            const float zt  = __half2float(xzh[row * (2 * DINNER) + DINNER + d]);
            float Bv[16], Cv[16];
            load_bc16(xdbl + row * XPROJ_N + DTRANK, Bv);
            load_bc16(xdbl + row * XPROJ_N + DTRANK + DSTATE, Cv);
            const float dtu = dtt * ut;
            const float E = __expf(dtt * a0);
            float dA = E;
            float acc = 0.f;
#pragma unroll
            for (int n = 0; n < DSTATE; n++) {
                h[n] = fmaf(dA, h[n], dtu * Bv[n]);
                acc = fmaf(h[n], Cv[n], acc);
                dA *= E;
            }
            float yv = fmaf(ut, Dd, acc);
            float sz = zt / (1.f + __expf(-zt));
            yh[row * DINNER + d] = __float2half(yv * sz);
        }
    } else {
        for (int l = l0; l < l0 + CLEN; l++) {
            const size_t row = (size_t)b * LSEQ + l;
            const float ut  = __half2float(uh[row * DINNER + d]);
            const float dtt = __half2float(dth[row * DINNER + d]);
            const float zt  = __half2float(xzh[row * (2 * DINNER) + DINNER + d]);
            float Bv[16], Cv[16];
            load_bc16(xdbl + row * XPROJ_N + DTRANK, Bv);
            load_bc16(xdbl + row * XPROJ_N + DTRANK + DSTATE, Cv);
            const float dtu = dtt * ut;
            float acc = 0.f;
#pragma unroll
            for (int n = 0; n < DSTATE; n++) {
                h[n] = fmaf(__expf(dtt * A[n]), h[n], dtu * Bv[n]);
                acc = fmaf(h[n], Cv[n], acc);
            }
            float yv = fmaf(ut, Dd, acc);
            float sz = zt / (1.f + __expf(-zt));
            yh[row * DINNER + d] = __float2half(yv * sz);
        }
    }
}

// ---------------------------------------------------------------------------
// Host side
// ---------------------------------------------------------------------------
typedef CUresult (*PFN_tmencode)(CUtensorMap*, CUtensorMapDataType, cuuint32_t,
                                 void*, const cuuint64_t*, const cuuint64_t*,
                                 const cuuint32_t*, const cuuint32_t*,
                                 CUtensorMapInterleave, CUtensorMapSwizzle,
                                 CUtensorMapL2promotion, CUtensorMapFloatOOBfill);

static PFN_tmencode get_encoder() {
    void* fn = nullptr;
    cudaDriverEntryPointQueryResult st;
#if CUDART_VERSION >= 12050
    if (cudaGetDriverEntryPointByVersion("cuTensorMapEncodeTiled", &fn, 12000,
                                         cudaEnableDefault, &st) != cudaSuccess)
        fn = nullptr;
#else
    if (cudaGetDriverEntryPoint("cuTensorMapEncodeTiled", &fn,
                                cudaEnableDefault, &st) != cudaSuccess)
        fn = nullptr;
#endif
    if (st != cudaDriverEntryPointSuccess) fn = nullptr;
    return (PFN_tmencode)fn;
}

static bool enc2d(PFN_tmencode f, CUtensorMap* m, void* p,
                  uint64_t d0, uint64_t d1, uint64_t strideBytes) {
    cuuint64_t dims[2] = {(cuuint64_t)d0, (cuuint64_t)d1};
    cuuint64_t str[1]  = {(cuuint64_t)strideBytes};
    cuuint32_t box[2]  = {64, 128};   // 64 halves = 128B rows (SW128)
    cuuint32_t es[2]   = {1, 1};
    return f(m, CU_TENSOR_MAP_DATA_TYPE_UINT16, 2, p, dims, str, box, es,
             CU_TENSOR_MAP_INTERLEAVE_NONE, CU_TENSOR_MAP_SWIZZLE_128B,
             CU_TENSOR_MAP_L2_PROMOTION_L2_128B,
             CU_TENSOR_MAP_FLOAT_OOB_FILL_NONE) == CUDA_SUCCESS;
}

extern "C" void kernel_launch(void* const* d_in, const int* in_sizes, int n_in,
                              void* d_out, int out_size)
{
    const float* x          = (const float*)d_in[0];
    const float* in_proj_w  = (const float*)d_in[1];
    const float* conv_w     = (const float*)d_in[2];
    const float* conv_b     = (const float*)d_in[3];
    const float* x_proj_w   = (const float*)d_in[4];
    const float* dt_proj_w  = (const float*)d_in[5];
    const float* dt_proj_b  = (const float*)d_in[6];
    const float* A_log      = (const float*)d_in[7];
    const float* Dp         = (const float*)d_in[8];
    const float* out_proj_w = (const float*)d_in[9];
    float* out = (float*)d_out;

    float *xdbl, *xp4, *hp, *hs, *Ss;
    __half *xzh, *uh, *dtin_h, *dth, *yh, *xh, *w1h, *w2h, *w3h, *w4h;
    cudaGetSymbolAddress((void**)&xzh,    g_xzh);
    cudaGetSymbolAddress((void**)&uh,     g_uh);
    cudaGetSymbolAddress((void**)&xdbl,   g_xdbl);
    cudaGetSymbolAddress((void**)&xp4,    g_xp4);
    cudaGetSymbolAddress((void**)&dtin_h, g_dtin_h);
    cudaGetSymbolAddress((void**)&dth,    g_dth);
    cudaGetSymbolAddress((void**)&yh,     g_yh);
    cudaGetSymbolAddress((void**)&xh,     g_xh);
    cudaGetSymbolAddress((void**)&w1h,    g_w1h);
    cudaGetSymbolAddress((void**)&w2h,    g_w2h);
    cudaGetSymbolAddress((void**)&w3h,    g_w3h);
    cudaGetSymbolAddress((void**)&w4h,    g_w4h);
    cudaGetSymbolAddress((void**)&hp,     g_hpart);
    cudaGetSymbolAddress((void**)&hs,     g_hstart);
    cudaGetSymbolAddress((void**)&Ss,     g_S);

    // TMA tensor maps (host-only, encoded at capture time)
    PFN_tmencode enc = get_encoder();
    CUtensorMap tmXA, tmW1, tmUA, tmW2, tmDA, tmW3, tmYA, tmW4;
    bool use_tma = (enc != nullptr);
    if (use_tma) {
        use_tma = use_tma && enc2d(enc, &tmXA, xh,     DMODEL, ROWS,      DMODEL * 2);
        use_tma = use_tma && enc2d(enc, &tmW1, w1h,    DMODEL, 2*DINNER,  DMODEL * 2);
        use_tma = use_tma && enc2d(enc, &tmUA, uh,     DINNER, ROWS,      DINNER * 2);
        use_tma = use_tma && enc2d(enc, &tmW2, w2h,    DINNER, XPROJ_N,   DINNER * 2);
        use_tma = use_tma && enc2d(enc, &tmDA, dtin_h, DTRANK, ROWS,      DTRANK * 2);
        use_tma = use_tma && enc2d(enc, &tmW3, w3h,    DTRANK, DINNER,    DTRANK * 2);
        use_tma = use_tma && enc2d(enc, &tmYA, yh,     DINNER, ROWS,      DINNER * 2);
        use_tma = use_tma && enc2d(enc, &tmW4, w4h,    DINNER, DMODEL,    DINNER * 2);
    }

    if (use_tma) {
        cudaFuncSetAttribute(tma_hgemm<0>, cudaFuncAttributeMaxDynamicSharedMemorySize, TSMEM_BYTES);
        cudaFuncSetAttribute(tma_hgemm<3>, cudaFuncAttributeMaxDynamicSharedMemorySize, TSMEM_BYTES);
        cudaFuncSetAttribute(tma_hgemm<4>, cudaFuncAttributeMaxDynamicSharedMemorySize, TSMEM_BYTES);
        cudaFuncSetAttribute(tma_hgemm<5>, cudaFuncAttributeMaxDynamicSharedMemorySize, TSMEM_BYTES);
    } else {
        cudaFuncSetAttribute(hgemm_nt<0>, cudaFuncAttributeMaxDynamicSharedMemorySize, HSMEM_BYTES);
        cudaFuncSetAttribute(hgemm_nt<3>, cudaFuncAttributeMaxDynamicSharedMemorySize, HSMEM_BYTES);
        cudaFuncSetAttribute(hgemm_nt<4>, cudaFuncAttributeMaxDynamicSharedMemorySize, HSMEM_BYTES);
        cudaFuncSetAttribute(hgemm_nt<5>, cudaFuncAttributeMaxDynamicSharedMemorySize, HSMEM_BYTES);
    }

    // 0) fused fp16 conversion of x + all weights (one launch)
    cvt_all_kernel<<<(NG_TOT + 255) / 256, 256>>>(x, xh, in_proj_w, w1h,
                                                  x_proj_w, w2h, dt_proj_w, w3h,
                                                  out_proj_w, w4h);

    // 1) xz = x @ in_proj_w^T -> fp16 [4096, 4096]
    if (use_tma)
        tma_hgemm<3><<<dim3(32, 32), 256, TSMEM_BYTES>>>(tmXA, tmW1, nullptr, nullptr, xzh,
                                           ROWS, 2 * DINNER, DMODEL, 2 * DINNER);
    else
        hgemm_nt<3><<<dim3(32, 32), 256, HSMEM_BYTES>>>(xh, w1h, nullptr, nullptr, xzh,
                                           ROWS, 2 * DINNER, DMODEL,
                                           DMODEL, DMODEL, 2 * DINNER);
    // 2) u = silu(causal_conv(xb) + b)   [4096, 2048]  (fp16, 2ch/thread)
    conv_silu_kernel<<<(ROWS * DINNER / 2) / 256, 256>>>(xzh, conv_w, conv_b, uh);
    // 3) x_dbl = u @ x_proj_w^T          [4096, 160]  split-K x4 + reduce
    if (use_tma)
        tma_hgemm<4><<<dim3(2, 32, KSPLIT), 256, TSMEM_BYTES>>>(tmUA, tmW2, xp4, nullptr, nullptr,
                                           ROWS, XPROJ_N, DINNER / KSPLIT, XPROJ_N);
    else
        hgemm_nt<4><<<dim3(2, 32, KSPLIT), 256, HSMEM_BYTES>>>(uh, w2h, xp4, nullptr, nullptr,
                                           ROWS, XPROJ_N, DINNER / KSPLIT,
                                           DINNER, DINNER, XPROJ_N);
    xproj_reduce<<<(XPN / 4 + 255) / 256, 256>>>(xp4, xdbl, dtin_h);
    // 4) dt = softplus(dt_in @ dt_proj_w^T + b) -> fp16  [4096, 2048]
    if (use_tma)
        tma_hgemm<5><<<dim3(16, 32), 256, TSMEM_BYTES>>>(tmDA, tmW3, nullptr, dt_proj_b, dth,
                                           ROWS, DINNER, DTRANK, DINNER);
    else
        hgemm_nt<5><<<dim3(16, 32), 256, HSMEM_BYTES>>>(dtin_h, w3h, nullptr, dt_proj_b, dth,
                                           ROWS, DINNER, DTRANK,
                                           DTRANK, DTRANK, DINNER);
    // 5) chunked selective scan -> y (fp16)
    scan_pass1<<<dim3(DINNER / 128, CHUNKS, BATCH), 128>>>(uh, dth, xdbl, A_log, hp, Ss);
    scan_combine<<<dim3(DINNER / 128, DSTATE, BATCH), 128>>>(A_log, Ss, hp, hs);
    scan_pass2<<<dim3(DINNER / 128, CHUNKS, BATCH), 128>>>(uh, dth, xdbl, xzh, A_log, Dp, hs, yh);
    // 6) out = y @ out_proj_w^T          [4096, 1024]
    if (use_tma)
        tma_hgemm<0><<<dim3(8, 32), 256, TSMEM_BYTES>>>(tmYA, tmW4, out, nullptr, nullptr,
                                           ROWS, DMODEL, DINNER, DMODEL);
    else
        hgemm_nt<0><<<dim3(8, 32), 256, HSMEM_BYTES>>>(yh, w4h, out, nullptr, nullptr,
                                           ROWS, DMODEL, DINNER,
                                           DINNER, DINNER, DMODEL);
}